// round 1
// baseline (speedup 1.0000x reference)
#include <cuda_runtime.h>

// Shapes (fixed by the problem)
#define B_  2
#define S_  128
#define D_  256
#define H_  8
#define E_  32
#define BH_ (B_*H_)   // 16

// Scratch (device globals: no allocation allowed)
__device__ float g_xs[BH_ * S_ * E_];   // softmax'd projected activations, [bh][s][e]
__device__ float g_o [BH_ * S_ * E_];   // attn @ x result, [bh][s][e]

// ---------------------------------------------------------------------------
// K1: x = inputs @ w_in^T + b_in ; per-head softmax over E ; write g_xs
// grid = B*S blocks (one per token row), 256 threads
// ---------------------------------------------------------------------------
__global__ void k_proj_softmax(const float* __restrict__ inp,
                               const float* __restrict__ w_in,
                               const float* __restrict__ b_in) {
    __shared__ float x_sh[D_];
    __shared__ float y_sh[D_];
    const int row = blockIdx.x;            // b*S + s
    const int t   = threadIdx.x;
    const int w   = t >> 5, l = t & 31;

    x_sh[t] = inp[row * D_ + t];
    __syncthreads();

    // warp w computes outputs e = w*32 + k via coalesced loads + shfl reduce
    for (int k = 0; k < 32; ++k) {
        const int e = (w << 5) + k;
        const float* wr = w_in + e * D_;
        float acc = 0.f;
        #pragma unroll
        for (int i = 0; i < 8; ++i)
            acc = fmaf(x_sh[l + 32 * i], wr[l + 32 * i], acc);
        #pragma unroll
        for (int o = 16; o > 0; o >>= 1)
            acc += __shfl_xor_sync(0xffffffffu, acc, o);
        if (l == 0) y_sh[e] = acc + b_in[e];
    }
    __syncthreads();

    // per-head softmax: warp w == head h, lane l == element e within head
    float val = y_sh[(w << 5) + l];
    float mx = val;
    #pragma unroll
    for (int o = 16; o > 0; o >>= 1)
        mx = fmaxf(mx, __shfl_xor_sync(0xffffffffu, mx, o));
    float p = __expf(val - mx);
    float sm = p;
    #pragma unroll
    for (int o = 16; o > 0; o >>= 1)
        sm += __shfl_xor_sync(0xffffffffu, sm, o);
    const float r = p / sm;

    const int b = row >> 7, s = row & (S_ - 1);
    g_xs[(((b << 3) + w) * S_ + s) * E_ + l] = r;
}

// ---------------------------------------------------------------------------
// K2: spline scores + softmax over j + out = attn @ x  (the hot kernel)
// grid = (S, BH) ; 128 threads (thread t owns column j = t)
// Constants (1 + E^2) dropped: softmax is shift-invariant; Σ a*b = 1 (softmax rows).
// ---------------------------------------------------------------------------
__global__ void k_spline_attn() {
    __shared__ float xsh[S_ * 33];       // padded rows: bank-conflict-free
    __shared__ float attn_sh[S_];
    __shared__ float red_mx[4];
    __shared__ float red_sm[4];
    __shared__ float pacc[4][E_];

    const int i  = blockIdx.x;
    const int bh = blockIdx.y;
    const int t  = threadIdx.x;

    const float* base = g_xs + bh * (S_ * E_);
    #pragma unroll
    for (int idx = t; idx < S_ * E_; idx += 128) {
        const int r_ = idx >> 5, c_ = idx & 31;
        xsh[r_ * 33 + c_] = base[idx];
    }
    __syncthreads();

    // Thread t = column j. Its x-row lives in registers.
    float v[E_];
    #pragma unroll
    for (int f = 0; f < E_; ++f) v[f] = xsh[t * 33 + f];

    const float* u = xsh + i * 33;
    const float c6 = -(1.0f / 6.0f);
    float s0 = 0.f, s1 = 0.f, s2 = 0.f, s3 = 0.f;   // break FMA dep chain

    for (int e = 0; e < E_; ++e) {
        const float a  = u[e];         // LDS broadcast
        const float ha = 0.5f * a;
        #pragma unroll
        for (int f = 0; f < E_; f += 4) {
            {   float vf = v[f+0]; float m = fminf(a, vf);
                float tt = fmaf(m * m, c6, ha * vf); s0 = fmaf(m, tt, s0); }
            {   float vf = v[f+1]; float m = fminf(a, vf);
                float tt = fmaf(m * m, c6, ha * vf); s1 = fmaf(m, tt, s1); }
            {   float vf = v[f+2]; float m = fminf(a, vf);
                float tt = fmaf(m * m, c6, ha * vf); s2 = fmaf(m, tt, s2); }
            {   float vf = v[f+3]; float m = fminf(a, vf);
                float tt = fmaf(m * m, c6, ha * vf); s3 = fmaf(m, tt, s3); }
        }
    }
    const float logit = ((s0 + s1) + (s2 + s3)) * (1.0f / (float)E_);

    // block softmax over 128 logits
    const int w = t >> 5, l = t & 31;
    float mx = logit;
    #pragma unroll
    for (int o = 16; o > 0; o >>= 1)
        mx = fmaxf(mx, __shfl_xor_sync(0xffffffffu, mx, o));
    if (l == 0) red_mx[w] = mx;
    __syncthreads();
    mx = fmaxf(fmaxf(red_mx[0], red_mx[1]), fmaxf(red_mx[2], red_mx[3]));

    const float p = __expf(logit - mx);
    float sm = p;
    #pragma unroll
    for (int o = 16; o > 0; o >>= 1)
        sm += __shfl_xor_sync(0xffffffffu, sm, o);
    if (l == 0) red_sm[w] = sm;
    __syncthreads();
    sm = (red_sm[0] + red_sm[1]) + (red_sm[2] + red_sm[3]);

    attn_sh[t] = p / sm;
    __syncthreads();

    // out[i, e] = sum_j attn[j] * x[j, e]  -- 4 partial strips of 32 j each
    {
        const int e = t & 31, part = t >> 5;
        float acc = 0.f;
        #pragma unroll
        for (int j0 = 0; j0 < 32; ++j0) {
            const int j = part * 32 + j0;
            acc = fmaf(attn_sh[j], xsh[j * 33 + e], acc);   // broadcast + conflict-free
        }
        pacc[part][e] = acc;
    }
    __syncthreads();
    if (t < E_) {
        const float r = (pacc[0][t] + pacc[1][t]) + (pacc[2][t] + pacc[3][t]);
        g_o[(bh * S_ + i) * E_ + t] = r;
    }
}

// ---------------------------------------------------------------------------
// K3: out = o @ w_out^T + b_out   (o regathered from [bh][s][e] layout)
// grid = B*S, 256 threads
// ---------------------------------------------------------------------------
__global__ void k_out_proj(const float* __restrict__ w_out,
                           const float* __restrict__ b_out,
                           float* __restrict__ out) {
    __shared__ float x_sh[D_];
    const int row = blockIdx.x;
    const int t   = threadIdx.x;
    const int b = row >> 7, s = row & (S_ - 1);
    const int h = t >> 5, e = t & 31;

    x_sh[t] = g_o[(((b << 3) + h) * S_ + s) * E_ + e];
    __syncthreads();

    const int w = t >> 5, l = t & 31;
    for (int k = 0; k < 32; ++k) {
        const int eo = (w << 5) + k;
        const float* wr = w_out + eo * D_;
        float acc = 0.f;
        #pragma unroll
        for (int i = 0; i < 8; ++i)
            acc = fmaf(x_sh[l + 32 * i], wr[l + 32 * i], acc);
        #pragma unroll
        for (int o = 16; o > 0; o >>= 1)
            acc += __shfl_xor_sync(0xffffffffu, acc, o);
        if (l == 0) out[row * D_ + eo] = acc + b_out[eo];
    }
}

extern "C" void kernel_launch(void* const* d_in, const int* in_sizes, int n_in,
                              void* d_out, int out_size) {
    const float* inp   = (const float*)d_in[0];
    const float* w_in  = (const float*)d_in[1];
    const float* b_in  = (const float*)d_in[2];
    const float* w_out = (const float*)d_in[3];
    const float* b_out = (const float*)d_in[4];
    float* out = (float*)d_out;
    (void)in_sizes; (void)n_in; (void)out_size;

    k_proj_softmax<<<B_ * S_, 256>>>(inp, w_in, b_in);
    k_spline_attn<<<dim3(S_, BH_), 128>>>();
    k_out_proj<<<B_ * S_, 256>>>(w_out, b_out, out);
}